// round 1
// baseline (speedup 1.0000x reference)
#include <cuda_runtime.h>
#include <cstddef>

#define BATCH 2
#define SEQ 2048
#define EMB 4096
#define NHEAD 32
#define HDIM 128
#define QKV_COLS (3 * EMB)

// Scratch (allocation-free rule: __device__ globals)
__device__ float g_qkv[(size_t)BATCH * SEQ * QKV_COLS];   // [B*S, 12288]
__device__ float g_y[(size_t)BATCH * SEQ * EMB];          // [B*S, 4096]

// ---------------------------------------------------------------------------
// SGEMM (NN, fp32): C[M,N] = A[M,K] @ B[K,N], all row-major, dims % 128 == 0,
// K % 16 == 0. 128x128 tile, BK=16, 256 threads, 8x8 per-thread microtile.
// ---------------------------------------------------------------------------
__global__ __launch_bounds__(256) void sgemm_nn(
    const float* __restrict__ A, const float* __restrict__ B,
    float* __restrict__ C, int M, int N, int K)
{
    __shared__ float As[16][132];   // transposed A tile, padded (bank + 16B align)
    __shared__ float Bs[16][128];

    const int tid = threadIdx.x;
    const int bx = blockIdx.x;      // N tiles
    const int by = blockIdx.y;      // M tiles
    const int tx = tid & 15;
    const int ty = tid >> 4;

    const int arow  = tid >> 2;          // 0..63
    const int acol4 = (tid & 3) << 2;    // 0,4,8,12
    const int brow  = tid >> 5;          // 0..7
    const int bcol4 = (tid & 31) << 2;   // 0..124

    const float* Ab = A + (size_t)by * 128 * K;
    const float* Bb = B + (size_t)bx * 128;

    float acc[8][8];
#pragma unroll
    for (int i = 0; i < 8; i++)
#pragma unroll
        for (int j = 0; j < 8; j++) acc[i][j] = 0.f;

    for (int k0 = 0; k0 < K; k0 += 16) {
#pragma unroll
        for (int i = 0; i < 2; i++) {
            float4 va = *(const float4*)(Ab + (size_t)(arow + i * 64) * K + k0 + acol4);
            As[acol4 + 0][arow + i * 64] = va.x;
            As[acol4 + 1][arow + i * 64] = va.y;
            As[acol4 + 2][arow + i * 64] = va.z;
            As[acol4 + 3][arow + i * 64] = va.w;
            *(float4*)(&Bs[brow + i * 8][bcol4]) =
                *(const float4*)(Bb + (size_t)(k0 + brow + i * 8) * N + bcol4);
        }
        __syncthreads();
#pragma unroll
        for (int k = 0; k < 16; k++) {
            float af[8], bf[8];
            *(float4*)(af)     = *(const float4*)(&As[k][ty * 8]);
            *(float4*)(af + 4) = *(const float4*)(&As[k][ty * 8 + 4]);
            *(float4*)(bf)     = *(const float4*)(&Bs[k][tx * 8]);
            *(float4*)(bf + 4) = *(const float4*)(&Bs[k][tx * 8 + 4]);
#pragma unroll
            for (int i = 0; i < 8; i++)
#pragma unroll
                for (int j = 0; j < 8; j++)
                    acc[i][j] = fmaf(af[i], bf[j], acc[i][j]);
        }
        __syncthreads();
    }

#pragma unroll
    for (int i = 0; i < 8; i++) {
        float* Cr = C + (size_t)(by * 128 + ty * 8 + i) * N + bx * 128 + tx * 8;
        *(float4*)(Cr)     = make_float4(acc[i][0], acc[i][1], acc[i][2], acc[i][3]);
        *(float4*)(Cr + 4) = make_float4(acc[i][4], acc[i][5], acc[i][6], acc[i][7]);
    }
}

// ---------------------------------------------------------------------------
// RoPE in-place on q and k halves of g_qkv.
// One thread per (b, s, h, j) rotary pair; handles both q and k.
// ---------------------------------------------------------------------------
__global__ __launch_bounds__(256) void rope_kernel(
    float* __restrict__ qkv, const float* __restrict__ fcos,
    const float* __restrict__ fsin)
{
    const int idx = blockIdx.x * 256 + threadIdx.x;   // 2^23 total
    const int j = idx & 63;
    const int h = (idx >> 6) & 31;
    const int s = (idx >> 11) & 2047;
    const int b = idx >> 22;

    const float c  = fcos[s * 64 + j];
    const float sn = fsin[s * 64 + j];

    const size_t base = (size_t)(b * SEQ + s) * QKV_COLS + h * HDIM + 2 * j;

    float qr = qkv[base], qi = qkv[base + 1];
    qkv[base]     = qr * c - qi * sn;
    qkv[base + 1] = qr * sn + qi * c;

    float kr = qkv[base + EMB], ki = qkv[base + EMB + 1];
    qkv[base + EMB]     = kr * c - ki * sn;
    qkv[base + EMB + 1] = kr * sn + ki * c;
}

// ---------------------------------------------------------------------------
// Flash attention (causal, fp32). Block = 64 query rows of one (b,h).
// grid = (SEQ/64, BATCH*NHEAD), 256 threads.
// Smem: Qs/Ks transposed [128][68], Vs [64][132], Ps [64][65], row stats.
// ---------------------------------------------------------------------------
#define FA_QK_PAD 68
#define FA_V_PAD 132
#define FA_P_PAD 65
#define FA_SMEM_FLOATS (128 * FA_QK_PAD * 2 + 64 * FA_V_PAD + 64 * FA_P_PAD + 192)
#define FA_SMEM_BYTES (FA_SMEM_FLOATS * 4)

__global__ __launch_bounds__(256) void flash_kernel(
    const float* __restrict__ qkv, float* __restrict__ y)
{
    extern __shared__ float sm[];
    float* Qs    = sm;                        // [128][68] d-major
    float* Ks    = Qs + 128 * FA_QK_PAD;      // [128][68] d-major
    float* Vs    = Ks + 128 * FA_QK_PAD;      // [64][132] kv-major
    float* Ps    = Vs + 64 * FA_V_PAD;        // [64][65]
    float* row_m = Ps + 64 * FA_P_PAD;
    float* row_l = row_m + 64;
    float* row_a = row_l + 64;

    const int tid = threadIdx.x;
    const int qb  = blockIdx.x;
    const int bh  = blockIdx.y;
    const int b   = bh >> 5;
    const int h   = bh & 31;
    const int q0  = qb * 64;
    const float scale = 0.08838834764831845f;  // 1/sqrt(128)

    const size_t base = (size_t)b * SEQ * QKV_COLS + (size_t)h * HDIM;
    const float* Qg = qkv + base;
    const float* Kg = qkv + base + EMB;
    const float* Vg = qkv + base + 2 * EMB;

    // Load Q tile (transposed into smem, pre-scaled). Conflict-free smem stores.
    for (int v = tid; v < 64 * 32; v += 256) {
        int qi = v & 63;
        int d4 = (v >> 6) << 2;
        float4 t = *(const float4*)(Qg + (size_t)(q0 + qi) * QKV_COLS + d4);
        Qs[(d4 + 0) * FA_QK_PAD + qi] = t.x * scale;
        Qs[(d4 + 1) * FA_QK_PAD + qi] = t.y * scale;
        Qs[(d4 + 2) * FA_QK_PAD + qi] = t.z * scale;
        Qs[(d4 + 3) * FA_QK_PAD + qi] = t.w * scale;
    }
    if (tid < 64) { row_m[tid] = -1e30f; row_l[tid] = 0.f; }

    float acc[4][8];
#pragma unroll
    for (int i = 0; i < 4; i++)
#pragma unroll
        for (int j = 0; j < 8; j++) acc[i][j] = 0.f;

    const int sty = tid >> 4, stx = tid & 15;     // score phase: 4x4 per thread
    const int ptx = tid & 15, pty = tid >> 4;     // PV phase: rows pty*4, cols ptx*8

    const int ntiles = qb + 1;
    for (int t0 = 0; t0 < ntiles; t0++) {
        const int k0 = t0 * 64;
        __syncthreads();  // protect Ks/Vs/Ps reuse

        // Load K (transposed) and V tiles
        for (int v = tid; v < 64 * 32; v += 256) {
            int kj = v & 63;
            int d4 = (v >> 6) << 2;
            float4 tk = *(const float4*)(Kg + (size_t)(k0 + kj) * QKV_COLS + d4);
            Ks[(d4 + 0) * FA_QK_PAD + kj] = tk.x;
            Ks[(d4 + 1) * FA_QK_PAD + kj] = tk.y;
            Ks[(d4 + 2) * FA_QK_PAD + kj] = tk.z;
            Ks[(d4 + 3) * FA_QK_PAD + kj] = tk.w;
            float4 tv = *(const float4*)(Vg + (size_t)(k0 + kj) * QKV_COLS + d4);
            *(float4*)(Vs + kj * FA_V_PAD + d4) = tv;
        }
        __syncthreads();

        // Phase 1: scores S = (Q*scale) @ K^T, 4x4 microtile per thread
        float s[4][4];
#pragma unroll
        for (int i = 0; i < 4; i++)
#pragma unroll
            for (int j = 0; j < 4; j++) s[i][j] = 0.f;
        for (int k = 0; k < 128; k++) {
            float4 a  = *(const float4*)(Qs + k * FA_QK_PAD + sty * 4);
            float4 bb = *(const float4*)(Ks + k * FA_QK_PAD + stx * 4);
            float av[4] = {a.x, a.y, a.z, a.w};
            float bv[4] = {bb.x, bb.y, bb.z, bb.w};
#pragma unroll
            for (int i = 0; i < 4; i++)
#pragma unroll
                for (int j = 0; j < 4; j++)
                    s[i][j] = fmaf(av[i], bv[j], s[i][j]);
        }
        // causal mask + write to Ps
#pragma unroll
        for (int i = 0; i < 4; i++) {
            int gi = q0 + sty * 4 + i;
#pragma unroll
            for (int j = 0; j < 4; j++) {
                int gj = k0 + stx * 4 + j;
                Ps[(sty * 4 + i) * FA_P_PAD + stx * 4 + j] =
                    (gj <= gi) ? s[i][j] : -1e30f;
            }
        }
        __syncthreads();

        // Softmax bookkeeping: 4 threads per row
        {
            const int r = tid >> 2, part = tid & 3;
            float mloc = -1e30f;
            for (int c = part * 16; c < part * 16 + 16; c++)
                mloc = fmaxf(mloc, Ps[r * FA_P_PAD + c]);
            mloc = fmaxf(mloc, __shfl_xor_sync(0xffffffffu, mloc, 1));
            mloc = fmaxf(mloc, __shfl_xor_sync(0xffffffffu, mloc, 2));
            float mnew = fmaxf(row_m[r], mloc);
            float lloc = 0.f;
            for (int c = part * 16; c < part * 16 + 16; c++) {
                float p = __expf(Ps[r * FA_P_PAD + c] - mnew);
                Ps[r * FA_P_PAD + c] = p;
                lloc += p;
            }
            lloc += __shfl_xor_sync(0xffffffffu, lloc, 1);
            lloc += __shfl_xor_sync(0xffffffffu, lloc, 2);
            if (part == 0) {
                float alpha = __expf(row_m[r] - mnew);
                row_a[r] = alpha;
                row_l[r] = row_l[r] * alpha + lloc;
                row_m[r] = mnew;
            }
        }
        __syncthreads();

        // Phase 2: acc = acc*alpha + P @ V
#pragma unroll
        for (int i = 0; i < 4; i++) {
            float al = row_a[pty * 4 + i];
#pragma unroll
            for (int d = 0; d < 8; d++) acc[i][d] *= al;
        }
        for (int j = 0; j < 64; j++) {
            float4 v0 = *(const float4*)(Vs + j * FA_V_PAD + ptx * 8);
            float4 v1 = *(const float4*)(Vs + j * FA_V_PAD + ptx * 8 + 4);
#pragma unroll
            for (int i = 0; i < 4; i++) {
                float p = Ps[(pty * 4 + i) * FA_P_PAD + j];
                acc[i][0] = fmaf(p, v0.x, acc[i][0]);
                acc[i][1] = fmaf(p, v0.y, acc[i][1]);
                acc[i][2] = fmaf(p, v0.z, acc[i][2]);
                acc[i][3] = fmaf(p, v0.w, acc[i][3]);
                acc[i][4] = fmaf(p, v1.x, acc[i][4]);
                acc[i][5] = fmaf(p, v1.y, acc[i][5]);
                acc[i][6] = fmaf(p, v1.z, acc[i][6]);
                acc[i][7] = fmaf(p, v1.w, acc[i][7]);
            }
        }
    }

    // Epilogue: y[b, q, h*128 + d] = acc / l
#pragma unroll
    for (int i = 0; i < 4; i++) {
        int qi = q0 + pty * 4 + i;
        float inv = 1.f / row_l[pty * 4 + i];
        float* yr = y + (size_t)(b * SEQ + qi) * EMB + h * HDIM + ptx * 8;
        *(float4*)(yr) = make_float4(acc[i][0] * inv, acc[i][1] * inv,
                                     acc[i][2] * inv, acc[i][3] * inv);
        *(float4*)(yr + 4) = make_float4(acc[i][4] * inv, acc[i][5] * inv,
                                         acc[i][6] * inv, acc[i][7] * inv);
    }
}

// ---------------------------------------------------------------------------
extern "C" void kernel_launch(void* const* d_in, const int* in_sizes, int n_in,
                              void* d_out, int out_size)
{
    (void)in_sizes; (void)n_in; (void)out_size;
    const float* x       = (const float*)d_in[0];
    const float* w_atten = (const float*)d_in[1];
    const float* w_proj  = (const float*)d_in[2];
    const float* fcos    = (const float*)d_in[3];
    const float* fsin    = (const float*)d_in[4];
    float* out = (float*)d_out;

    float *qkv_ptr, *y_ptr;
    cudaGetSymbolAddress((void**)&qkv_ptr, g_qkv);
    cudaGetSymbolAddress((void**)&y_ptr, g_y);

    const int M = BATCH * SEQ;  // 4096

    // 1) QKV projection
    dim3 g1(QKV_COLS / 128, M / 128);
    sgemm_nn<<<g1, 256>>>(x, w_atten, qkv_ptr, M, QKV_COLS, EMB);

    // 2) RoPE on q, k (in place)
    rope_kernel<<<(BATCH * SEQ * NHEAD * 64) / 256, 256>>>(qkv_ptr, fcos, fsin);

    // 3) Causal flash attention
    cudaFuncSetAttribute(flash_kernel,
                         cudaFuncAttributeMaxDynamicSharedMemorySize,
                         FA_SMEM_BYTES);
    dim3 gf(SEQ / 64, BATCH * NHEAD);
    flash_kernel<<<gf, 256, FA_SMEM_BYTES>>>(qkv_ptr, y_ptr);

    // 4) Output projection
    dim3 g2(EMB / 128, M / 128);
    sgemm_nn<<<g2, 256>>>(y_ptr, w_proj, out, M, EMB, EMB);
}

// round 3
// speedup vs baseline: 1.6539x; 1.6539x over previous
#include <cuda_runtime.h>
#include <cuda_bf16.h>
#include <cstdint>
#include <cstddef>

#define BATCH 2
#define SEQ 2048
#define EMB 4096
#define NHEAD 32
#define HDIM 128
#define QKV_COLS (3 * EMB)
#define MROWS (BATCH * SEQ)

// ---------------------------------------------------------------------------
// Scratch (__device__ globals, allocation-free rule)
// ---------------------------------------------------------------------------
__device__ float g_qkv[(size_t)MROWS * QKV_COLS];
__device__ float g_y[(size_t)MROWS * EMB];
__device__ __nv_bfloat16 g_x_hi[(size_t)MROWS * EMB];
__device__ __nv_bfloat16 g_x_lo[(size_t)MROWS * EMB];
__device__ __nv_bfloat16 g_wa_hi[(size_t)QKV_COLS * EMB];  // [N,K] transposed
__device__ __nv_bfloat16 g_wa_lo[(size_t)QKV_COLS * EMB];
__device__ __nv_bfloat16 g_wp_hi[(size_t)EMB * EMB];
__device__ __nv_bfloat16 g_wp_lo[(size_t)EMB * EMB];
__device__ __nv_bfloat16 g_y_hi[(size_t)MROWS * EMB];
__device__ __nv_bfloat16 g_y_lo[(size_t)MROWS * EMB];

// ---------------------------------------------------------------------------
// PTX helpers (sm_80+ features only: ldmatrix, mma.sync, cp.async)
// ---------------------------------------------------------------------------
__device__ __forceinline__ uint32_t smem_to_u32(const void* smem_ptr) {
    uint32_t addr;
    asm("{ .reg .u64 tmp; cvta.to.shared.u64 tmp, %1; cvt.u32.u64 %0, tmp; }"
        : "=r"(addr) : "l"(smem_ptr));
    return addr;
}

#define SMEM_SWIZZLE_128B(byte_offset) \
    ((byte_offset) ^ (((byte_offset) >> 3) & 0x70))

__device__ __forceinline__ void cp_async16(uint32_t dst, const void* src) {
    asm volatile("cp.async.cg.shared.global [%0], [%1], 16;"
                 :: "r"(dst), "l"(src) : "memory");
}
#define CP_ASYNC_COMMIT() asm volatile("cp.async.commit_group;" ::: "memory")
#define CP_ASYNC_WAIT(n)  asm volatile("cp.async.wait_group %0;" :: "n"(n) : "memory")

#define LDSM_X4(r0, r1, r2, r3, addr) \
    asm volatile("ldmatrix.sync.aligned.m8n8.x4.shared.b16 {%0,%1,%2,%3}, [%4];" \
                 : "=r"(r0), "=r"(r1), "=r"(r2), "=r"(r3) : "r"(addr))

__device__ __forceinline__ void mma16816(float* c, const uint32_t* a,
                                         uint32_t b0, uint32_t b1) {
    asm volatile(
        "mma.sync.aligned.m16n8k16.row.col.f32.bf16.bf16.f32 "
        "{%0,%1,%2,%3}, {%4,%5,%6,%7}, {%8,%9}, {%0,%1,%2,%3};"
        : "+f"(c[0]), "+f"(c[1]), "+f"(c[2]), "+f"(c[3])
        : "r"(a[0]), "r"(a[1]), "r"(a[2]), "r"(a[3]), "r"(b0), "r"(b1));
}

// ---------------------------------------------------------------------------
// Split fp32 -> bf16 hi/lo (elementwise, vectorized)
// ---------------------------------------------------------------------------
__global__ __launch_bounds__(256) void split_f32_kernel(
    const float4* __restrict__ in, uint2* __restrict__ hi, uint2* __restrict__ lo, int n4)
{
    int i = blockIdx.x * 256 + threadIdx.x;
    if (i >= n4) return;
    float4 v = in[i];
    float f[4] = {v.x, v.y, v.z, v.w};
    uint32_t hw[2] = {0, 0}, lw[2] = {0, 0};
#pragma unroll
    for (int j = 0; j < 4; j++) {
        __nv_bfloat16 h = __float2bfloat16(f[j]);
        __nv_bfloat16 l = __float2bfloat16(f[j] - __bfloat162float(h));
        hw[j >> 1] |= ((uint32_t)__bfloat16_as_ushort(h)) << ((j & 1) * 16);
        lw[j >> 1] |= ((uint32_t)__bfloat16_as_ushort(l)) << ((j & 1) * 16);
    }
    hi[i] = make_uint2(hw[0], hw[1]);
    lo[i] = make_uint2(lw[0], lw[1]);
}

// ---------------------------------------------------------------------------
// Split + transpose weights: w [K,N] fp32 (row-major) -> hiT/loT [N,K] bf16
// ---------------------------------------------------------------------------
__global__ __launch_bounds__(256) void split_wT_kernel(
    const float* __restrict__ w, __nv_bfloat16* __restrict__ hiT,
    __nv_bfloat16* __restrict__ loT, int K, int N)
{
    __shared__ float t[32][33];
    const int bx = blockIdx.x;   // N tile
    const int by = blockIdx.y;   // K tile
    const int tx = threadIdx.x;  // 0..31
    const int ty = threadIdx.y;  // 0..7
#pragma unroll
    for (int i = 0; i < 4; i++)
        t[ty + 8 * i][tx] = w[(size_t)(by * 32 + ty + 8 * i) * N + bx * 32 + tx];
    __syncthreads();
#pragma unroll
    for (int i = 0; i < 4; i++) {
        int nn = ty + 8 * i;
        float v = t[tx][nn];
        __nv_bfloat16 h = __float2bfloat16(v);
        __nv_bfloat16 l = __float2bfloat16(v - __bfloat162float(h));
        size_t o = (size_t)(bx * 32 + nn) * K + by * 32 + tx;
        hiT[o] = h;
        loT[o] = l;
    }
}

// ---------------------------------------------------------------------------
// HMMA bf16 split-GEMM: C[M,N] (fp32) = sum over 3 segments of
//   Aseg[M,K](bf16) @ Bseg[N,K]^T(bf16), fp32 accumulate in registers.
// CTA tile 128x128, BK=64, 3-stage cp.async pipeline, 256 threads (8 warps).
// Warp grid 4(M) x 2(N): warp tile 32x64. mma.sync m16n8k16.
// Smem per stage: A 128x64 bf16 (16KB, 128B rows SW128) + B same = 32KB.
// ---------------------------------------------------------------------------
#define STAGES 3
#define STAGE_BYTES 32768
#define GEMM_SMEM (1024 + STAGES * STAGE_BYTES)

__global__ __launch_bounds__(256) void tc_gemm(
    const __nv_bfloat16* __restrict__ A_hi, const __nv_bfloat16* __restrict__ A_lo,
    const __nv_bfloat16* __restrict__ B_hi, const __nv_bfloat16* __restrict__ B_lo,
    float* __restrict__ C, int M, int N, int K)
{
    extern __shared__ char smem_raw[];
    const uint32_t smem_base = smem_to_u32(smem_raw);
    const uint32_t tile_base = (smem_base + 1023) & ~1023u;

    const int tiles_m = M >> 7;
    const int tiles_n = N >> 7;

    // grouped raster for L2 reuse
    const int G = 8;
    int pid = blockIdx.x;
    int npg = G * tiles_n;
    int gid_g = pid / npg;
    int first_m = gid_g * G;
    int gsz = tiles_m - first_m;
    if (gsz > G) gsz = G;
    int pm = first_m + (pid % gsz);
    int pn = (pid % npg) / gsz;
    const int m0 = pm << 7;
    const int n0 = pn << 7;

    const int tid  = threadIdx.x;
    const int wid  = tid >> 5;
    const int lane = tid & 31;

    // ------- loader mapping: thread t loads 4x16B of A row + 4x16B of B row
    const int ldr_row  = tid >> 1;          // 0..127
    const int ldr_half = (tid & 1) * 4;     // chunk base 0 or 4 (16B units)
    uint32_t swz[4];
#pragma unroll
    for (int i = 0; i < 4; i++) {
        uint32_t off = (uint32_t)ldr_row * 128 + (ldr_half + i) * 16;
        swz[i] = SMEM_SWIZZLE_128B(off);
    }
    const size_t aoff = (size_t)(m0 + ldr_row) * K + ldr_half * 8;
    const size_t boff = (size_t)(n0 + ldr_row) * K + ldr_half * 8;

    const __nv_bfloat16* segA[3] = {A_hi, A_hi, A_lo};
    const __nv_bfloat16* segB[3] = {B_hi, B_lo, B_hi};

    const int kc = K >> 6;
    const int n_chunks = 3 * kc;

    // ------- compute mapping
    const int warp_m = wid & 3;             // *32
    const int warp_n = wid >> 2;            // *64
    const int rA = lane & 15;
    const int cA = lane >> 4;
    const uint32_t xorA = (uint32_t)(rA & 7) << 4;
    const uint32_t rowTermA = (uint32_t)(warp_m * 32 + rA) * 128;
    const int rB = (lane & 7) + ((lane >> 4) & 1) * 8;
    const int cB = (lane >> 3) & 1;
    const uint32_t xorB = (uint32_t)(lane & 7) << 4;
    const uint32_t rowTermB = (uint32_t)(warp_n * 64 + rB) * 128;

    float acc[2][8][4];
#pragma unroll
    for (int mt = 0; mt < 2; mt++)
#pragma unroll
        for (int nt = 0; nt < 8; nt++)
#pragma unroll
            for (int i = 0; i < 4; i++) acc[mt][nt][i] = 0.f;

    // ------- pipeline
    auto load_stage = [&](int c) {
        const int s = c % STAGES;
        const int seg = c / kc;
        const int k0 = (c - seg * kc) << 6;
        const __nv_bfloat16* gA = segA[seg] + aoff + k0;
        const __nv_bfloat16* gB = segB[seg] + boff + k0;
        const uint32_t dA = tile_base + s * STAGE_BYTES;
        const uint32_t dB = dA + 16384;
#pragma unroll
        for (int i = 0; i < 4; i++) cp_async16(dA + swz[i], gA + i * 8);
#pragma unroll
        for (int i = 0; i < 4; i++) cp_async16(dB + swz[i], gB + i * 8);
        CP_ASYNC_COMMIT();
    };

#pragma unroll
    for (int c = 0; c < STAGES - 1; c++) load_stage(c);

    for (int c = 0; c < n_chunks; c++) {
        if (c + 1 < n_chunks) { CP_ASYNC_WAIT(1); } else { CP_ASYNC_WAIT(0); }
        __syncthreads();
        if (c + STAGES - 1 < n_chunks) load_stage(c + STAGES - 1);

        const int s = c % STAGES;
        const uint32_t sA = tile_base + s * STAGE_BYTES;
        const uint32_t sB = sA + 16384;

#pragma unroll
        for (int kk = 0; kk < 4; kk++) {
            uint32_t a[2][4];
#pragma unroll
            for (int mt = 0; mt < 2; mt++) {
                uint32_t addr = sA + rowTermA + mt * 2048 +
                                ((((uint32_t)(kk * 2 + cA) << 4)) ^ xorA);
                LDSM_X4(a[mt][0], a[mt][1], a[mt][2], a[mt][3], addr);
            }
            uint32_t b[4][4];
#pragma unroll
            for (int np = 0; np < 4; np++) {
                uint32_t addr = sB + rowTermB + np * 2048 +
                                ((((uint32_t)(kk * 2 + cB) << 4)) ^ xorB);
                LDSM_X4(b[np][0], b[np][1], b[np][2], b[np][3], addr);
            }
#pragma unroll
            for (int mt = 0; mt < 2; mt++)
#pragma unroll
                for (int nt = 0; nt < 8; nt++)
                    mma16816(acc[mt][nt], a[mt],
                             b[nt >> 1][(nt & 1) * 2], b[nt >> 1][(nt & 1) * 2 + 1]);
        }
        __syncthreads();
    }

    // ------- epilogue: registers -> gmem (fp32)
    const int egid = lane >> 2;
    const int etig = lane & 3;
#pragma unroll
    for (int mt = 0; mt < 2; mt++) {
#pragma unroll
        for (int nt = 0; nt < 8; nt++) {
            int row = m0 + warp_m * 32 + mt * 16 + egid;
            int col = n0 + warp_n * 64 + nt * 8 + etig * 2;
            *(float2*)(C + (size_t)row * N + col) =
                make_float2(acc[mt][nt][0], acc[mt][nt][1]);
            *(float2*)(C + (size_t)(row + 8) * N + col) =
                make_float2(acc[mt][nt][2], acc[mt][nt][3]);
        }
    }
}

// ---------------------------------------------------------------------------
// RoPE in-place on q and k halves of g_qkv
// ---------------------------------------------------------------------------
__global__ __launch_bounds__(256) void rope_kernel(
    float* __restrict__ qkv, const float* __restrict__ fcos,
    const float* __restrict__ fsin)
{
    const int idx = blockIdx.x * 256 + threadIdx.x;
    const int j = idx & 63;
    const int h = (idx >> 6) & 31;
    const int s = (idx >> 11) & 2047;
    const int b = idx >> 22;

    const float c  = fcos[s * 64 + j];
    const float sn = fsin[s * 64 + j];

    const size_t base = (size_t)(b * SEQ + s) * QKV_COLS + h * HDIM + 2 * j;

    float qr = qkv[base], qi = qkv[base + 1];
    qkv[base]     = qr * c - qi * sn;
    qkv[base + 1] = qr * sn + qi * c;

    float kr = qkv[base + EMB], ki = qkv[base + EMB + 1];
    qkv[base + EMB]     = kr * c - ki * sn;
    qkv[base + EMB + 1] = kr * sn + ki * c;
}

// ---------------------------------------------------------------------------
// Flash attention (causal, fp32) — unchanged from round 1
// ---------------------------------------------------------------------------
#define FA_QK_PAD 68
#define FA_V_PAD 132
#define FA_P_PAD 65
#define FA_SMEM_FLOATS (128 * FA_QK_PAD * 2 + 64 * FA_V_PAD + 64 * FA_P_PAD + 192)
#define FA_SMEM_BYTES (FA_SMEM_FLOATS * 4)

__global__ __launch_bounds__(256) void flash_kernel(
    const float* __restrict__ qkv, float* __restrict__ y)
{
    extern __shared__ float sm[];
    float* Qs    = sm;
    float* Ks    = Qs + 128 * FA_QK_PAD;
    float* Vs    = Ks + 128 * FA_QK_PAD;
    float* Ps    = Vs + 64 * FA_V_PAD;
    float* row_m = Ps + 64 * FA_P_PAD;
    float* row_l = row_m + 64;
    float* row_a = row_l + 64;

    const int tid = threadIdx.x;
    const int qb  = blockIdx.x;
    const int bh  = blockIdx.y;
    const int b   = bh >> 5;
    const int h   = bh & 31;
    const int q0  = qb * 64;
    const float scale = 0.08838834764831845f;

    const size_t base = (size_t)b * SEQ * QKV_COLS + (size_t)h * HDIM;
    const float* Qg = qkv + base;
    const float* Kg = qkv + base + EMB;
    const float* Vg = qkv + base + 2 * EMB;

    for (int v = tid; v < 64 * 32; v += 256) {
        int qi = v & 63;
        int d4 = (v >> 6) << 2;
        float4 t = *(const float4*)(Qg + (size_t)(q0 + qi) * QKV_COLS + d4);
        Qs[(d4 + 0) * FA_QK_PAD + qi] = t.x * scale;
        Qs[(d4 + 1) * FA_QK_PAD + qi] = t.y * scale;
        Qs[(d4 + 2) * FA_QK_PAD + qi] = t.z * scale;
        Qs[(d4 + 3) * FA_QK_PAD + qi] = t.w * scale;
    }
    if (tid < 64) { row_m[tid] = -1e30f; row_l[tid] = 0.f; }

    float acc[4][8];
#pragma unroll
    for (int i = 0; i < 4; i++)
#pragma unroll
        for (int j = 0; j < 8; j++) acc[i][j] = 0.f;

    const int sty = tid >> 4, stx = tid & 15;
    const int ptx = tid & 15, pty = tid >> 4;

    const int ntiles = qb + 1;
    for (int t0 = 0; t0 < ntiles; t0++) {
        const int k0 = t0 * 64;
        __syncthreads();

        for (int v = tid; v < 64 * 32; v += 256) {
            int kj = v & 63;
            int d4 = (v >> 6) << 2;
            float4 tk = *(const float4*)(Kg + (size_t)(k0 + kj) * QKV_COLS + d4);
            Ks[(d4 + 0) * FA_QK_PAD + kj] = tk.x;
            Ks[(d4 + 1) * FA_QK_PAD + kj] = tk.y;
            Ks[(d4 + 2) * FA_QK_PAD + kj] = tk.z;
            Ks[(d4 + 3) * FA_QK_PAD + kj] = tk.w;
            float4 tv = *(const float4*)(Vg + (size_t)(k0 + kj) * QKV_COLS + d4);
            *(float4*)(Vs + kj * FA_V_PAD + d4) = tv;
        }
        __syncthreads();

        float s[4][4];
#pragma unroll
        for (int i = 0; i < 4; i++)
#pragma unroll
            for (int j = 0; j < 4; j++) s[i][j] = 0.f;
        for (int k = 0; k < 128; k++) {
            float4 a  = *(const float4*)(Qs + k * FA_QK_PAD + sty * 4);
            float4 bb = *(const float4*)(Ks + k * FA_QK_PAD + stx * 4);
            float av[4] = {a.x, a.y, a.z, a.w};
            float bv[4] = {bb.x, bb.y, bb.z, bb.w};
#pragma unroll
            for (int i = 0; i < 4; i++)
#pragma unroll
                for (int j = 0; j < 4; j++)
                    s[i][j] = fmaf(av[i], bv[j], s[i][j]);
        }
#pragma unroll
        for (int i = 0; i < 4; i++) {
            int gi = q0 + sty * 4 + i;
#pragma unroll
            for (int j = 0; j < 4; j++) {
                int gj = k0 + stx * 4 + j;
                Ps[(sty * 4 + i) * FA_P_PAD + stx * 4 + j] =
                    (gj <= gi) ? s[i][j] : -1e30f;
            }
        }
        __syncthreads();

        {
            const int r = tid >> 2, part = tid & 3;
            float mloc = -1e30f;
            for (int c = part * 16; c < part * 16 + 16; c++)
                mloc = fmaxf(mloc, Ps[r * FA_P_PAD + c]);
            mloc = fmaxf(mloc, __shfl_xor_sync(0xffffffffu, mloc, 1));
            mloc = fmaxf(mloc, __shfl_xor_sync(0xffffffffu, mloc, 2));
            float mnew = fmaxf(row_m[r], mloc);
            float lloc = 0.f;
            for (int c = part * 16; c < part * 16 + 16; c++) {
                float p = __expf(Ps[r * FA_P_PAD + c] - mnew);
                Ps[r * FA_P_PAD + c] = p;
                lloc += p;
            }
            lloc += __shfl_xor_sync(0xffffffffu, lloc, 1);
            lloc += __shfl_xor_sync(0xffffffffu, lloc, 2);
            if (part == 0) {
                float alpha = __expf(row_m[r] - mnew);
                row_a[r] = alpha;
                row_l[r] = row_l[r] * alpha + lloc;
                row_m[r] = mnew;
            }
        }
        __syncthreads();

#pragma unroll
        for (int i = 0; i < 4; i++) {
            float al = row_a[pty * 4 + i];
#pragma unroll
            for (int d = 0; d < 8; d++) acc[i][d] *= al;
        }
        for (int j = 0; j < 64; j++) {
            float4 v0 = *(const float4*)(Vs + j * FA_V_PAD + ptx * 8);
            float4 v1 = *(const float4*)(Vs + j * FA_V_PAD + ptx * 8 + 4);
#pragma unroll
            for (int i = 0; i < 4; i++) {
                float p = Ps[(pty * 4 + i) * FA_P_PAD + j];
                acc[i][0] = fmaf(p, v0.x, acc[i][0]);
                acc[i][1] = fmaf(p, v0.y, acc[i][1]);
                acc[i][2] = fmaf(p, v0.z, acc[i][2]);
                acc[i][3] = fmaf(p, v0.w, acc[i][3]);
                acc[i][4] = fmaf(p, v1.x, acc[i][4]);
                acc[i][5] = fmaf(p, v1.y, acc[i][5]);
                acc[i][6] = fmaf(p, v1.z, acc[i][6]);
                acc[i][7] = fmaf(p, v1.w, acc[i][7]);
            }
        }
    }

#pragma unroll
    for (int i = 0; i < 4; i++) {
        int qi = q0 + pty * 4 + i;
        float inv = 1.f / row_l[pty * 4 + i];
        float* yr = y + (size_t)(b * SEQ + qi) * EMB + h * HDIM + ptx * 8;
        *(float4*)(yr) = make_float4(acc[i][0] * inv, acc[i][1] * inv,
                                     acc[i][2] * inv, acc[i][3] * inv);
        *(float4*)(yr + 4) = make_float4(acc[i][4] * inv, acc[i][5] * inv,
                                         acc[i][6] * inv, acc[i][7] * inv);
    }
}

// ---------------------------------------------------------------------------
extern "C" void kernel_launch(void* const* d_in, const int* in_sizes, int n_in,
                              void* d_out, int out_size)
{
    (void)in_sizes; (void)n_in; (void)out_size;
    const float* x       = (const float*)d_in[0];
    const float* w_atten = (const float*)d_in[1];
    const float* w_proj  = (const float*)d_in[2];
    const float* fcos    = (const float*)d_in[3];
    const float* fsin    = (const float*)d_in[4];
    float* out = (float*)d_out;

    float *qkv_ptr, *y_ptr;
    __nv_bfloat16 *x_hi, *x_lo, *wa_hi, *wa_lo, *wp_hi, *wp_lo, *y_hi, *y_lo;
    cudaGetSymbolAddress((void**)&qkv_ptr, g_qkv);
    cudaGetSymbolAddress((void**)&y_ptr, g_y);
    cudaGetSymbolAddress((void**)&x_hi, g_x_hi);
    cudaGetSymbolAddress((void**)&x_lo, g_x_lo);
    cudaGetSymbolAddress((void**)&wa_hi, g_wa_hi);
    cudaGetSymbolAddress((void**)&wa_lo, g_wa_lo);
    cudaGetSymbolAddress((void**)&wp_hi, g_wp_hi);
    cudaGetSymbolAddress((void**)&wp_lo, g_wp_lo);
    cudaGetSymbolAddress((void**)&y_hi, g_y_hi);
    cudaGetSymbolAddress((void**)&y_lo, g_y_lo);

    cudaFuncSetAttribute(tc_gemm, cudaFuncAttributeMaxDynamicSharedMemorySize,
                         GEMM_SMEM);
    cudaFuncSetAttribute(flash_kernel, cudaFuncAttributeMaxDynamicSharedMemorySize,
                         FA_SMEM_BYTES);

    // 1) split x into bf16 hi/lo
    {
        int n4 = MROWS * EMB / 4;
        split_f32_kernel<<<(n4 + 255) / 256, 256>>>(
            (const float4*)x, (uint2*)x_hi, (uint2*)x_lo, n4);
    }
    // 2) split+transpose weights
    split_wT_kernel<<<dim3(QKV_COLS / 32, EMB / 32), dim3(32, 8)>>>(
        w_atten, wa_hi, wa_lo, EMB, QKV_COLS);
    split_wT_kernel<<<dim3(EMB / 32, EMB / 32), dim3(32, 8)>>>(
        w_proj, wp_hi, wp_lo, EMB, EMB);

    // 3) QKV projection on tensor cores (HMMA)
    tc_gemm<<<(MROWS / 128) * (QKV_COLS / 128), 256, GEMM_SMEM>>>(
        x_hi, x_lo, wa_hi, wa_lo, qkv_ptr, MROWS, QKV_COLS, EMB);

    // 4) RoPE
    rope_kernel<<<(BATCH * SEQ * NHEAD * 64) / 256, 256>>>(qkv_ptr, fcos, fsin);

    // 5) Flash attention (fp32)
    dim3 gf(SEQ / 64, BATCH * NHEAD);
    flash_kernel<<<gf, 256, FA_SMEM_BYTES>>>(qkv_ptr, y_ptr);

    // 6) split y, then output projection on tensor cores
    {
        int n4 = MROWS * EMB / 4;
        split_f32_kernel<<<(n4 + 255) / 256, 256>>>(
            (const float4*)y_ptr, (uint2*)y_hi, (uint2*)y_lo, n4);
    }
    tc_gemm<<<(MROWS / 128) * (EMB / 128), 256, GEMM_SMEM>>>(
        y_hi, y_lo, wp_hi, wp_lo, out, MROWS, EMB, EMB);
}

// round 4
// speedup vs baseline: 2.3170x; 1.4010x over previous
#include <cuda_runtime.h>
#include <cuda_bf16.h>
#include <cstdint>
#include <cstddef>

#define BATCH 2
#define SEQ 2048
#define EMB 4096
#define NHEAD 32
#define HDIM 128
#define QKV_COLS (3 * EMB)
#define MROWS (BATCH * SEQ)

// ---------------------------------------------------------------------------
// Scratch (__device__ globals, allocation-free rule)
// ---------------------------------------------------------------------------
__device__ float g_qkv[(size_t)MROWS * QKV_COLS];
__device__ __nv_bfloat16 g_x_hi[(size_t)MROWS * EMB];
__device__ __nv_bfloat16 g_x_lo[(size_t)MROWS * EMB];
__device__ __nv_bfloat16 g_wa_hi[(size_t)QKV_COLS * EMB];  // [N,K] transposed
__device__ __nv_bfloat16 g_wa_lo[(size_t)QKV_COLS * EMB];
__device__ __nv_bfloat16 g_wp_hi[(size_t)EMB * EMB];
__device__ __nv_bfloat16 g_wp_lo[(size_t)EMB * EMB];
__device__ __nv_bfloat16 g_y_hi[(size_t)MROWS * EMB];
__device__ __nv_bfloat16 g_y_lo[(size_t)MROWS * EMB];
// rope-split Q/K/V, [B,S,H,D] bf16
__device__ __nv_bfloat16 g_q_hi[(size_t)MROWS * EMB];
__device__ __nv_bfloat16 g_q_lo[(size_t)MROWS * EMB];
__device__ __nv_bfloat16 g_k_hi[(size_t)MROWS * EMB];
__device__ __nv_bfloat16 g_k_lo[(size_t)MROWS * EMB];
__device__ __nv_bfloat16 g_v_hi[(size_t)MROWS * EMB];
__device__ __nv_bfloat16 g_v_lo[(size_t)MROWS * EMB];

// ---------------------------------------------------------------------------
// PTX helpers (sm_80+ features only: ldmatrix, mma.sync, cp.async)
// ---------------------------------------------------------------------------
__device__ __forceinline__ uint32_t smem_to_u32(const void* smem_ptr) {
    uint32_t addr;
    asm("{ .reg .u64 tmp; cvta.to.shared.u64 tmp, %1; cvt.u32.u64 %0, tmp; }"
        : "=r"(addr) : "l"(smem_ptr));
    return addr;
}

#define SMEM_SWIZZLE_128B(byte_offset) \
    ((byte_offset) ^ (((byte_offset) >> 3) & 0x70))

__device__ __forceinline__ void cp_async16(uint32_t dst, const void* src) {
    asm volatile("cp.async.cg.shared.global [%0], [%1], 16;"
                 :: "r"(dst), "l"(src) : "memory");
}
#define CP_ASYNC_COMMIT() asm volatile("cp.async.commit_group;" ::: "memory")
#define CP_ASYNC_WAIT(n)  asm volatile("cp.async.wait_group %0;" :: "n"(n) : "memory")

#define LDSM_X4(r0, r1, r2, r3, addr) \
    asm volatile("ldmatrix.sync.aligned.m8n8.x4.shared.b16 {%0,%1,%2,%3}, [%4];" \
                 : "=r"(r0), "=r"(r1), "=r"(r2), "=r"(r3) : "r"(addr))

#define LDSM_X4_T(r0, r1, r2, r3, addr) \
    asm volatile("ldmatrix.sync.aligned.m8n8.x4.trans.shared.b16 {%0,%1,%2,%3}, [%4];" \
                 : "=r"(r0), "=r"(r1), "=r"(r2), "=r"(r3) : "r"(addr))

__device__ __forceinline__ void mma16816(float* c, const uint32_t* a,
                                         uint32_t b0, uint32_t b1) {
    asm volatile(
        "mma.sync.aligned.m16n8k16.row.col.f32.bf16.bf16.f32 "
        "{%0,%1,%2,%3}, {%4,%5,%6,%7}, {%8,%9}, {%0,%1,%2,%3};"
        : "+f"(c[0]), "+f"(c[1]), "+f"(c[2]), "+f"(c[3])
        : "r"(a[0]), "r"(a[1]), "r"(a[2]), "r"(a[3]), "r"(b0), "r"(b1));
}

// pack two floats to bf16x2 (lo -> low half, hi -> high half)
__device__ __forceinline__ uint32_t pack_bf16(float lo, float hi) {
    return (uint32_t)__bfloat16_as_ushort(__float2bfloat16(lo)) |
           ((uint32_t)__bfloat16_as_ushort(__float2bfloat16(hi)) << 16);
}
// split one float into bf16 hi and residual-lo floats
__device__ __forceinline__ void split_hl(float v, float& h, float& l) {
    h = __bfloat162float(__float2bfloat16(v));
    l = v - h;
}

// ---------------------------------------------------------------------------
// Split fp32 -> bf16 hi/lo (elementwise, vectorized)
// ---------------------------------------------------------------------------
__global__ __launch_bounds__(256) void split_f32_kernel(
    const float4* __restrict__ in, uint2* __restrict__ hi, uint2* __restrict__ lo, int n4)
{
    int i = blockIdx.x * 256 + threadIdx.x;
    if (i >= n4) return;
    float4 v = in[i];
    float f[4] = {v.x, v.y, v.z, v.w};
    uint32_t hw[2] = {0, 0}, lw[2] = {0, 0};
#pragma unroll
    for (int j = 0; j < 4; j++) {
        __nv_bfloat16 h = __float2bfloat16(f[j]);
        __nv_bfloat16 l = __float2bfloat16(f[j] - __bfloat162float(h));
        hw[j >> 1] |= ((uint32_t)__bfloat16_as_ushort(h)) << ((j & 1) * 16);
        lw[j >> 1] |= ((uint32_t)__bfloat16_as_ushort(l)) << ((j & 1) * 16);
    }
    hi[i] = make_uint2(hw[0], hw[1]);
    lo[i] = make_uint2(lw[0], lw[1]);
}

// ---------------------------------------------------------------------------
// Split + transpose weights: w [K,N] fp32 (row-major) -> hiT/loT [N,K] bf16
// ---------------------------------------------------------------------------
__global__ __launch_bounds__(256) void split_wT_kernel(
    const float* __restrict__ w, __nv_bfloat16* __restrict__ hiT,
    __nv_bfloat16* __restrict__ loT, int K, int N)
{
    __shared__ float t[32][33];
    const int bx = blockIdx.x;   // N tile
    const int by = blockIdx.y;   // K tile
    const int tx = threadIdx.x;  // 0..31
    const int ty = threadIdx.y;  // 0..7
#pragma unroll
    for (int i = 0; i < 4; i++)
        t[ty + 8 * i][tx] = w[(size_t)(by * 32 + ty + 8 * i) * N + bx * 32 + tx];
    __syncthreads();
#pragma unroll
    for (int i = 0; i < 4; i++) {
        int nn = ty + 8 * i;
        float v = t[tx][nn];
        __nv_bfloat16 h = __float2bfloat16(v);
        __nv_bfloat16 l = __float2bfloat16(v - __bfloat162float(h));
        size_t o = (size_t)(bx * 32 + nn) * K + by * 32 + tx;
        hiT[o] = h;
        loT[o] = l;
    }
}

// ---------------------------------------------------------------------------
// HMMA bf16 split-GEMM (unchanged from round 3, verified)
// ---------------------------------------------------------------------------
#define STAGES 3
#define STAGE_BYTES 32768
#define GEMM_SMEM (1024 + STAGES * STAGE_BYTES)

__global__ __launch_bounds__(256) void tc_gemm(
    const __nv_bfloat16* __restrict__ A_hi, const __nv_bfloat16* __restrict__ A_lo,
    const __nv_bfloat16* __restrict__ B_hi, const __nv_bfloat16* __restrict__ B_lo,
    float* __restrict__ C, int M, int N, int K)
{
    extern __shared__ char smem_raw[];
    const uint32_t smem_base = smem_to_u32(smem_raw);
    const uint32_t tile_base = (smem_base + 1023) & ~1023u;

    const int tiles_m = M >> 7;
    const int tiles_n = N >> 7;

    const int G = 8;
    int pid = blockIdx.x;
    int npg = G * tiles_n;
    int gid_g = pid / npg;
    int first_m = gid_g * G;
    int gsz = tiles_m - first_m;
    if (gsz > G) gsz = G;
    int pm = first_m + (pid % gsz);
    int pn = (pid % npg) / gsz;
    const int m0 = pm << 7;
    const int n0 = pn << 7;

    const int tid  = threadIdx.x;
    const int wid  = tid >> 5;
    const int lane = tid & 31;

    const int ldr_row  = tid >> 1;
    const int ldr_half = (tid & 1) * 4;
    uint32_t swz[4];
#pragma unroll
    for (int i = 0; i < 4; i++) {
        uint32_t off = (uint32_t)ldr_row * 128 + (ldr_half + i) * 16;
        swz[i] = SMEM_SWIZZLE_128B(off);
    }
    const size_t aoff = (size_t)(m0 + ldr_row) * K + ldr_half * 8;
    const size_t boff = (size_t)(n0 + ldr_row) * K + ldr_half * 8;

    const __nv_bfloat16* segA[3] = {A_hi, A_hi, A_lo};
    const __nv_bfloat16* segB[3] = {B_hi, B_lo, B_hi};

    const int kc = K >> 6;
    const int n_chunks = 3 * kc;

    const int warp_m = wid & 3;
    const int warp_n = wid >> 2;
    const int rA = lane & 15;
    const int cA = lane >> 4;
    const uint32_t xorA = (uint32_t)(rA & 7) << 4;
    const uint32_t rowTermA = (uint32_t)(warp_m * 32 + rA) * 128;
    const int rB = (lane & 7) + ((lane >> 4) & 1) * 8;
    const int cB = (lane >> 3) & 1;
    const uint32_t xorB = (uint32_t)(lane & 7) << 4;
    const uint32_t rowTermB = (uint32_t)(warp_n * 64 + rB) * 128;

    float acc[2][8][4];
#pragma unroll
    for (int mt = 0; mt < 2; mt++)
#pragma unroll
        for (int nt = 0; nt < 8; nt++)
#pragma unroll
            for (int i = 0; i < 4; i++) acc[mt][nt][i] = 0.f;

    auto load_stage = [&](int c) {
        const int s = c % STAGES;
        const int seg = c / kc;
        const int k0 = (c - seg * kc) << 6;
        const __nv_bfloat16* gA = segA[seg] + aoff + k0;
        const __nv_bfloat16* gB = segB[seg] + boff + k0;
        const uint32_t dA = tile_base + s * STAGE_BYTES;
        const uint32_t dB = dA + 16384;
#pragma unroll
        for (int i = 0; i < 4; i++) cp_async16(dA + swz[i], gA + i * 8);
#pragma unroll
        for (int i = 0; i < 4; i++) cp_async16(dB + swz[i], gB + i * 8);
        CP_ASYNC_COMMIT();
    };

#pragma unroll
    for (int c = 0; c < STAGES - 1; c++) load_stage(c);

    for (int c = 0; c < n_chunks; c++) {
        if (c + 1 < n_chunks) { CP_ASYNC_WAIT(1); } else { CP_ASYNC_WAIT(0); }
        __syncthreads();
        if (c + STAGES - 1 < n_chunks) load_stage(c + STAGES - 1);

        const int s = c % STAGES;
        const uint32_t sA = tile_base + s * STAGE_BYTES;
        const uint32_t sB = sA + 16384;

#pragma unroll
        for (int kk = 0; kk < 4; kk++) {
            uint32_t a[2][4];
#pragma unroll
            for (int mt = 0; mt < 2; mt++) {
                uint32_t addr = sA + rowTermA + mt * 2048 +
                                ((((uint32_t)(kk * 2 + cA) << 4)) ^ xorA);
                LDSM_X4(a[mt][0], a[mt][1], a[mt][2], a[mt][3], addr);
            }
            uint32_t b[4][4];
#pragma unroll
            for (int np = 0; np < 4; np++) {
                uint32_t addr = sB + rowTermB + np * 2048 +
                                ((((uint32_t)(kk * 2 + cB) << 4)) ^ xorB);
                LDSM_X4(b[np][0], b[np][1], b[np][2], b[np][3], addr);
            }
#pragma unroll
            for (int mt = 0; mt < 2; mt++)
#pragma unroll
                for (int nt = 0; nt < 8; nt++)
                    mma16816(acc[mt][nt], a[mt],
                             b[nt >> 1][(nt & 1) * 2], b[nt >> 1][(nt & 1) * 2 + 1]);
        }
        __syncthreads();
    }

    const int egid = lane >> 2;
    const int etig = lane & 3;
#pragma unroll
    for (int mt = 0; mt < 2; mt++) {
#pragma unroll
        for (int nt = 0; nt < 8; nt++) {
            int row = m0 + warp_m * 32 + mt * 16 + egid;
            int col = n0 + warp_n * 64 + nt * 8 + etig * 2;
            *(float2*)(C + (size_t)row * N + col) =
                make_float2(acc[mt][nt][0], acc[mt][nt][1]);
            *(float2*)(C + (size_t)(row + 8) * N + col) =
                make_float2(acc[mt][nt][2], acc[mt][nt][3]);
        }
    }
}

// ---------------------------------------------------------------------------
// RoPE + split to bf16 hi/lo Q/K/V ([B,S,H,D]). Scale folded into Q.
// One thread per (b,s,h,j) rotary pair.
// ---------------------------------------------------------------------------
__global__ __launch_bounds__(256) void rope_split_kernel(
    const float* __restrict__ qkv, const float* __restrict__ fcos,
    const float* __restrict__ fsin,
    __nv_bfloat16* __restrict__ qh, __nv_bfloat16* __restrict__ ql,
    __nv_bfloat16* __restrict__ kh, __nv_bfloat16* __restrict__ kl,
    __nv_bfloat16* __restrict__ vh, __nv_bfloat16* __restrict__ vl)
{
    const int idx = blockIdx.x * 256 + threadIdx.x;   // B*S*H*64
    const int j = idx & 63;
    const int h = (idx >> 6) & 31;
    const int s = (idx >> 11) & 2047;
    const int b = idx >> 22;
    const float scale = 0.08838834764831845f;  // 1/sqrt(128)

    const float c  = fcos[s * 64 + j];
    const float sn = fsin[s * 64 + j];

    const size_t qbase = (size_t)(b * SEQ + s) * QKV_COLS + h * HDIM + 2 * j;
    float2 q = *(const float2*)(qkv + qbase);
    float2 k = *(const float2*)(qkv + qbase + EMB);
    float2 v = *(const float2*)(qkv + qbase + 2 * EMB);

    float qr = (q.x * c - q.y * sn) * scale;
    float qi = (q.x * sn + q.y * c) * scale;
    float kr = k.x * c - k.y * sn;
    float ki = k.x * sn + k.y * c;

    const size_t o = ((size_t)(b * SEQ + s) * NHEAD + h) * HDIM + 2 * j;
    float h0, l0, h1, l1;

    split_hl(qr, h0, l0); split_hl(qi, h1, l1);
    *(uint32_t*)(qh + o) = pack_bf16(h0, h1);
    *(uint32_t*)(ql + o) = pack_bf16(l0, l1);
    split_hl(kr, h0, l0); split_hl(ki, h1, l1);
    *(uint32_t*)(kh + o) = pack_bf16(h0, h1);
    *(uint32_t*)(kl + o) = pack_bf16(l0, l1);
    split_hl(v.x, h0, l0); split_hl(v.y, h1, l1);
    *(uint32_t*)(vh + o) = pack_bf16(h0, h1);
    *(uint32_t*)(vl + o) = pack_bf16(l0, l1);
}

// ---------------------------------------------------------------------------
// Tensor-core flash attention (causal). 128 threads = 4 warps, 64 q rows/CTA.
// QK^T: 3-pass bf16 hi/lo. PV: 3-pass with P hi/lo and V hi/lo.
// Smem: 6 tiles [64 rows][136 bf16] (272B rows, conflict-free for ldmatrix).
// Writes y directly as bf16 hi/lo for the projection GEMM.
// ---------------------------------------------------------------------------
#define FT_ROWB 272                 // bytes per smem row (128 data + 16 pad)
#define FT_SLOT (64 * FT_ROWB)      // 17408 B
#define FT_SMEM (6 * FT_SLOT + 128)

__device__ __forceinline__ void ft_load_tile(
    uint32_t dst, const __nv_bfloat16* __restrict__ g, int grow0, int h, int tid)
{
#pragma unroll
    for (int it = 0; it < 8; it++) {
        int c = tid + it * 128;
        int r = c >> 4, ch = c & 15;
        cp_async16(dst + r * FT_ROWB + ch * 16,
                   g + (size_t)(grow0 + r) * EMB + h * HDIM + ch * 8);
    }
}

__global__ __launch_bounds__(128, 2) void flash_tc(
    const __nv_bfloat16* __restrict__ qh_g, const __nv_bfloat16* __restrict__ ql_g,
    const __nv_bfloat16* __restrict__ kh_g, const __nv_bfloat16* __restrict__ kl_g,
    const __nv_bfloat16* __restrict__ vh_g, const __nv_bfloat16* __restrict__ vl_g,
    __nv_bfloat16* __restrict__ yh_g, __nv_bfloat16* __restrict__ yl_g)
{
    extern __shared__ char sm_raw[];
    const uint32_t base = (smem_to_u32(sm_raw) + 127) & ~127u;
    const uint32_t QH = base, QL = base + FT_SLOT;
    const uint32_t KH = base + 2 * FT_SLOT, KL = base + 3 * FT_SLOT;
    const uint32_t VH = base + 4 * FT_SLOT, VL = base + 5 * FT_SLOT;

    const int tid = threadIdx.x, wid = tid >> 5, lane = tid & 31;
    const int qb = (int)gridDim.x - 1 - (int)blockIdx.x;   // long blocks first
    const int bh = blockIdx.y;
    const int b = bh >> 5, h = bh & 31;
    const int q0 = qb * 64;
    const int growq = b * SEQ + q0;

    // ---- prologue: Q tiles -> smem -> register fragments
    ft_load_tile(QH, qh_g, growq, h, tid);
    ft_load_tile(QL, ql_g, growq, h, tid);
    CP_ASYNC_COMMIT();
    CP_ASYNC_WAIT(0);
    __syncthreads();

    const int wr = wid * 16;
    const int rA = lane & 15, cA = lane >> 4;
    uint32_t qfh[8][4], qfl[8][4];
#pragma unroll
    for (int kk = 0; kk < 8; kk++) {
        uint32_t ao = (uint32_t)(wr + rA) * FT_ROWB + kk * 32 + cA * 16;
        LDSM_X4(qfh[kk][0], qfh[kk][1], qfh[kk][2], qfh[kk][3], QH + ao);
        LDSM_X4(qfl[kk][0], qfl[kk][1], qfl[kk][2], qfl[kk][3], QL + ao);
    }

    const int rB = (lane & 7) + ((lane >> 4) & 1) * 8;   // K frag rows
    const int cB = (lane >> 3) & 1;
    const int vr = lane & 15;                            // V trans rows
    const int vc = lane >> 4;
    const int egid = lane >> 2, tig = lane & 3;

    float m0 = -1e30f, m1 = -1e30f, l0 = 0.f, l1 = 0.f;
    float accO[16][4];
#pragma unroll
    for (int nt = 0; nt < 16; nt++)
#pragma unroll
        for (int i = 0; i < 4; i++) accO[nt][i] = 0.f;

    for (int t = 0; t <= qb; t++) {
        const int k0 = t * 64;
        const int growk = b * SEQ + k0;
        __syncthreads();
        ft_load_tile(KH, kh_g, growk, h, tid);
        ft_load_tile(KL, kl_g, growk, h, tid);
        ft_load_tile(VH, vh_g, growk, h, tid);
        ft_load_tile(VL, vl_g, growk, h, tid);
        CP_ASYNC_COMMIT();
        CP_ASYNC_WAIT(0);
        __syncthreads();

        // ---- S = Q K^T (3-pass hi/lo)
        float accS[8][4];
#pragma unroll
        for (int nt = 0; nt < 8; nt++)
#pragma unroll
            for (int i = 0; i < 4; i++) accS[nt][i] = 0.f;

#pragma unroll
        for (int kk = 0; kk < 8; kk++) {
            uint32_t bh4[4][4], bl4[4][4];
#pragma unroll
            for (int np = 0; np < 4; np++) {
                uint32_t ao = (uint32_t)(np * 16 + rB) * FT_ROWB + kk * 32 + cB * 16;
                LDSM_X4(bh4[np][0], bh4[np][1], bh4[np][2], bh4[np][3], KH + ao);
                LDSM_X4(bl4[np][0], bl4[np][1], bl4[np][2], bl4[np][3], KL + ao);
            }
#pragma unroll
            for (int np = 0; np < 4; np++)
#pragma unroll
                for (int hf = 0; hf < 2; hf++) {
                    const int nt = np * 2 + hf;
                    mma16816(accS[nt], qfh[kk], bh4[np][hf * 2], bh4[np][hf * 2 + 1]);
                    mma16816(accS[nt], qfl[kk], bh4[np][hf * 2], bh4[np][hf * 2 + 1]);
                    mma16816(accS[nt], qfh[kk], bl4[np][hf * 2], bl4[np][hf * 2 + 1]);
                }
        }

        // ---- causal mask (diagonal tile only; k0 == q0 there)
        if (t == qb) {
            const int row0 = wr + egid, row1 = row0 + 8;
#pragma unroll
            for (int nt = 0; nt < 8; nt++) {
                const int c0 = nt * 8 + tig * 2, c1 = c0 + 1;
                if (c0 > row0) accS[nt][0] = -1e30f;
                if (c1 > row0) accS[nt][1] = -1e30f;
                if (c0 > row1) accS[nt][2] = -1e30f;
                if (c1 > row1) accS[nt][3] = -1e30f;
            }
        }

        // ---- online softmax (registers + shfl within 4-lane groups)
        float mx0 = -1e30f, mx1 = -1e30f;
#pragma unroll
        for (int nt = 0; nt < 8; nt++) {
            mx0 = fmaxf(mx0, fmaxf(accS[nt][0], accS[nt][1]));
            mx1 = fmaxf(mx1, fmaxf(accS[nt][2], accS[nt][3]));
        }
        mx0 = fmaxf(mx0, __shfl_xor_sync(0xffffffffu, mx0, 1));
        mx0 = fmaxf(mx0, __shfl_xor_sync(0xffffffffu, mx0, 2));
        mx1 = fmaxf(mx1, __shfl_xor_sync(0xffffffffu, mx1, 1));
        mx1 = fmaxf(mx1, __shfl_xor_sync(0xffffffffu, mx1, 2));

        const float mn0 = fmaxf(m0, mx0), mn1 = fmaxf(m1, mx1);
        const float a0 = __expf(m0 - mn0), a1 = __expf(m1 - mn1);
        m0 = mn0; m1 = mn1;

        float s0 = 0.f, s1 = 0.f;
#pragma unroll
        for (int nt = 0; nt < 8; nt++) {
            accS[nt][0] = __expf(accS[nt][0] - mn0);
            accS[nt][1] = __expf(accS[nt][1] - mn0);
            accS[nt][2] = __expf(accS[nt][2] - mn1);
            accS[nt][3] = __expf(accS[nt][3] - mn1);
            s0 += accS[nt][0] + accS[nt][1];
            s1 += accS[nt][2] + accS[nt][3];
        }
        s0 += __shfl_xor_sync(0xffffffffu, s0, 1);
        s0 += __shfl_xor_sync(0xffffffffu, s0, 2);
        s1 += __shfl_xor_sync(0xffffffffu, s1, 1);
        s1 += __shfl_xor_sync(0xffffffffu, s1, 2);
        l0 = l0 * a0 + s0;
        l1 = l1 * a1 + s1;

#pragma unroll
        for (int nt = 0; nt < 16; nt++) {
            accO[nt][0] *= a0; accO[nt][1] *= a0;
            accO[nt][2] *= a1; accO[nt][3] *= a1;
        }

        // ---- P fragments (hi/lo) from accS (C-frag -> A-frag repack)
        uint32_t pfh[4][4], pfl[4][4];
#pragma unroll
        for (int j = 0; j < 4; j++) {
#pragma unroll
            for (int u = 0; u < 2; u++) {
                const int nt = 2 * j + u;
                float h00, l00, h01, l01, h10, l10, h11, l11;
                split_hl(accS[nt][0], h00, l00);
                split_hl(accS[nt][1], h01, l01);
                split_hl(accS[nt][2], h10, l10);
                split_hl(accS[nt][3], h11, l11);
                pfh[j][u * 2]     = pack_bf16(h00, h01);
                pfh[j][u * 2 + 1] = pack_bf16(h10, h11);
                pfl[j][u * 2]     = pack_bf16(l00, l01);
                pfl[j][u * 2 + 1] = pack_bf16(l10, l11);
            }
        }

        // ---- O += P V (3-pass; V via ldmatrix.trans)
#pragma unroll
        for (int j = 0; j < 4; j++) {
#pragma unroll
            for (int np = 0; np < 8; np++) {
                uint32_t vh4[4], vl4[4];
                uint32_t ao = (uint32_t)(j * 16 + vr) * FT_ROWB + np * 32 + vc * 16;
                LDSM_X4_T(vh4[0], vh4[1], vh4[2], vh4[3], VH + ao);
                LDSM_X4_T(vl4[0], vl4[1], vl4[2], vl4[3], VL + ao);
                mma16816(accO[2 * np],     pfh[j], vh4[0], vh4[1]);
                mma16816(accO[2 * np],     pfl[j], vh4[0], vh4[1]);
                mma16816(accO[2 * np],     pfh[j], vl4[0], vl4[1]);
                mma16816(accO[2 * np + 1], pfh[j], vh4[2], vh4[3]);
                mma16816(accO[2 * np + 1], pfl[j], vh4[2], vh4[3]);
                mma16816(accO[2 * np + 1], pfh[j], vl4[2], vl4[3]);
            }
        }
    }

    // ---- epilogue: y = O / l, write bf16 hi/lo
    const float inv0 = 1.f / l0, inv1 = 1.f / l1;
    const size_t row0 = (size_t)(growq + wr + egid);
    const size_t row1 = row0 + 8;
#pragma unroll
    for (int nt = 0; nt < 16; nt++) {
        const int col = h * HDIM + nt * 8 + tig * 2;
        float v0 = accO[nt][0] * inv0, v1 = accO[nt][1] * inv0;
        float v2 = accO[nt][2] * inv1, v3 = accO[nt][3] * inv1;
        float hh, ll, hh2, ll2;
        split_hl(v0, hh, ll); split_hl(v1, hh2, ll2);
        *(uint32_t*)(yh_g + row0 * EMB + col) = pack_bf16(hh, hh2);
        *(uint32_t*)(yl_g + row0 * EMB + col) = pack_bf16(ll, ll2);
        split_hl(v2, hh, ll); split_hl(v3, hh2, ll2);
        *(uint32_t*)(yh_g + row1 * EMB + col) = pack_bf16(hh, hh2);
        *(uint32_t*)(yl_g + row1 * EMB + col) = pack_bf16(ll, ll2);
    }
}

// ---------------------------------------------------------------------------
extern "C" void kernel_launch(void* const* d_in, const int* in_sizes, int n_in,
                              void* d_out, int out_size)
{
    (void)in_sizes; (void)n_in; (void)out_size;
    const float* x       = (const float*)d_in[0];
    const float* w_atten = (const float*)d_in[1];
    const float* w_proj  = (const float*)d_in[2];
    const float* fcos    = (const float*)d_in[3];
    const float* fsin    = (const float*)d_in[4];
    float* out = (float*)d_out;

    float* qkv_ptr;
    __nv_bfloat16 *x_hi, *x_lo, *wa_hi, *wa_lo, *wp_hi, *wp_lo, *y_hi, *y_lo;
    __nv_bfloat16 *q_hi, *q_lo, *k_hi, *k_lo, *v_hi, *v_lo;
    cudaGetSymbolAddress((void**)&qkv_ptr, g_qkv);
    cudaGetSymbolAddress((void**)&x_hi, g_x_hi);
    cudaGetSymbolAddress((void**)&x_lo, g_x_lo);
    cudaGetSymbolAddress((void**)&wa_hi, g_wa_hi);
    cudaGetSymbolAddress((void**)&wa_lo, g_wa_lo);
    cudaGetSymbolAddress((void**)&wp_hi, g_wp_hi);
    cudaGetSymbolAddress((void**)&wp_lo, g_wp_lo);
    cudaGetSymbolAddress((void**)&y_hi, g_y_hi);
    cudaGetSymbolAddress((void**)&y_lo, g_y_lo);
    cudaGetSymbolAddress((void**)&q_hi, g_q_hi);
    cudaGetSymbolAddress((void**)&q_lo, g_q_lo);
    cudaGetSymbolAddress((void**)&k_hi, g_k_hi);
    cudaGetSymbolAddress((void**)&k_lo, g_k_lo);
    cudaGetSymbolAddress((void**)&v_hi, g_v_hi);
    cudaGetSymbolAddress((void**)&v_lo, g_v_lo);

    cudaFuncSetAttribute(tc_gemm, cudaFuncAttributeMaxDynamicSharedMemorySize,
                         GEMM_SMEM);
    cudaFuncSetAttribute(flash_tc, cudaFuncAttributeMaxDynamicSharedMemorySize,
                         FT_SMEM);

    // 1) split x into bf16 hi/lo
    {
        int n4 = MROWS * EMB / 4;
        split_f32_kernel<<<(n4 + 255) / 256, 256>>>(
            (const float4*)x, (uint2*)x_hi, (uint2*)x_lo, n4);
    }
    // 2) split+transpose weights
    split_wT_kernel<<<dim3(QKV_COLS / 32, EMB / 32), dim3(32, 8)>>>(
        w_atten, wa_hi, wa_lo, EMB, QKV_COLS);
    split_wT_kernel<<<dim3(EMB / 32, EMB / 32), dim3(32, 8)>>>(
        w_proj, wp_hi, wp_lo, EMB, EMB);

    // 3) QKV projection (HMMA)
    tc_gemm<<<(MROWS / 128) * (QKV_COLS / 128), 256, GEMM_SMEM>>>(
        x_hi, x_lo, wa_hi, wa_lo, qkv_ptr, MROWS, QKV_COLS, EMB);

    // 4) RoPE + bf16 hi/lo split of Q,K,V (scale folded into Q)
    rope_split_kernel<<<(BATCH * SEQ * NHEAD * 64) / 256, 256>>>(
        qkv_ptr, fcos, fsin, q_hi, q_lo, k_hi, k_lo, v_hi, v_lo);

    // 5) Tensor-core flash attention -> y (bf16 hi/lo)
    {
        dim3 gf(SEQ / 64, BATCH * NHEAD);
        flash_tc<<<gf, 128, FT_SMEM>>>(q_hi, q_lo, k_hi, k_lo, v_hi, v_lo,
                                       y_hi, y_lo);
    }

    // 6) Output projection (HMMA)
    tc_gemm<<<(MROWS / 128) * (EMB / 128), 256, GEMM_SMEM>>>(
        y_hi, y_lo, wp_hi, wp_lo, out, MROWS, EMB, EMB);
}